// round 12
// baseline (speedup 1.0000x reference)
#include <cuda_runtime.h>
#include <math.h>

// Problem shapes (fixed for this problem instance)
static constexpr int IN_F = 256;
static constexpr int H    = 96;
static constexpr int OUTF = 40;
static constexpr int NMAX = 50000;
static constexpr int EMAX = 800000;
static constexpr int HC4  = H / 4;   // 24 float4 chunks per row

// ---------------- scratch (device globals; no allocation allowed) ----------
__device__ float g_x0[(size_t)NMAX * H];   // fc1 output (initial residual)
__device__ float g_xc[(size_t)NMAX * H];   // current activation
__device__ float g_hb[(size_t)NMAX * H];   // h2 buffer
__device__ float g_dinv[NMAX];
__device__ int   g_deg[NMAX];              // zero-init at load; scan re-zeroes
__device__ int   g_off[NMAX + 1];          // CSR offsets (by dst/col)
__device__ int   g_cur[NMAX];              // fill cursors
__device__ int2  g_epack[EMAX];            // {src row, bits(weight)} CSR-ordered
__device__ float g_stats[2 * H];           // sum, sumsq (zeroed by bnfin)
__device__ float g_bn[2 * H];              // scale, shift per feature

// ---------------- fused fc1 + degree count (launch #1) ---------------------
__global__ __launch_bounds__(256, 2) void fc1_deg_kernel(
    const float* __restrict__ X, const float* __restrict__ W,
    const float* __restrict__ B, int N,
    const int* __restrict__ ei, int E, int fc1Blocks)
{
    if (blockIdx.x >= fc1Blocks) {
        int i = (blockIdx.x - fc1Blocks) * 256 + threadIdx.x;
        if (i < E) atomicAdd(&g_deg[ei[E + i]], 1);
        return;
    }
    __shared__ float Xs[32][132];   // [k][row]
    __shared__ float Ws[32][98];    // [k][col]
    const int tid = threadIdx.x;
    const int tx = tid & 15, ty = tid >> 4;
    const int row0 = blockIdx.x * 128;
    const int lr   = tid & 127;
    const int kgrp = tid >> 7;

    float acc[8][6];
#pragma unroll
    for (int r = 0; r < 8; r++)
#pragma unroll
        for (int c = 0; c < 6; c++) acc[r][c] = 0.f;

    for (int kc = 0; kc < IN_F; kc += 32) {
        {
            int gr = row0 + lr;
            const float* xp = X + (size_t)gr * IN_F + kc + kgrp * 16;
#pragma unroll
            for (int m = 0; m < 4; m++) {
                float4 v = (gr < N) ? *(const float4*)(xp + 4 * m)
                                    : make_float4(0.f, 0.f, 0.f, 0.f);
                int k = kgrp * 16 + 4 * m;
                Xs[k + 0][lr] = v.x;
                Xs[k + 1][lr] = v.y;
                Xs[k + 2][lr] = v.z;
                Xs[k + 3][lr] = v.w;
            }
        }
        {
            const float* wp = W + (size_t)kc * H + tid * 12;
#pragma unroll
            for (int m = 0; m < 3; m++) {
                float4 v = *(const float4*)(wp + 4 * m);
                int f = tid * 12 + 4 * m;
                int k = f / 96, j = f - 96 * k;
                Ws[k][j + 0] = v.x;
                Ws[k][j + 1] = v.y;
                Ws[k][j + 2] = v.z;
                Ws[k][j + 3] = v.w;
            }
        }
        __syncthreads();
#pragma unroll 8
        for (int kk = 0; kk < 32; kk++) {
            float4 A0 = *(const float4*)&Xs[kk][ty * 8];
            float4 A1 = *(const float4*)&Xs[kk][ty * 8 + 4];
            float2 B0 = *(const float2*)&Ws[kk][tx * 6];
            float2 B1 = *(const float2*)&Ws[kk][tx * 6 + 2];
            float2 B2 = *(const float2*)&Ws[kk][tx * 6 + 4];
            float a[8] = {A0.x, A0.y, A0.z, A0.w, A1.x, A1.y, A1.z, A1.w};
            float bv[6] = {B0.x, B0.y, B1.x, B1.y, B2.x, B2.y};
#pragma unroll
            for (int r = 0; r < 8; r++)
#pragma unroll
                for (int c = 0; c < 6; c++) acc[r][c] = fmaf(a[r], bv[c], acc[r][c]);
        }
        __syncthreads();
    }
#pragma unroll
    for (int r = 0; r < 8; r++) {
        int gr = row0 + ty * 8 + r;
        if (gr < N) {
#pragma unroll
            for (int c = 0; c < 6; c++) {
                int j = tx * 6 + c;
                float v = acc[r][c] + B[j];
                v = v > 0.f ? v : 0.f;
                g_x0[(size_t)gr * H + j] = v;
                g_xc[(size_t)gr * H + j] = v;
            }
        }
    }
}

// ---------------- scan (launch #2): off/cur/dinv; re-zeroes g_deg ----------
__global__ __launch_bounds__(1024) void scan_dinv_kernel(int N) {
    const int C = (N + 1023) / 1024;
    int t = threadIdx.x;
    int start = t * C;
    int end = start + C; if (end > N) end = N;
    int local = 0;
    for (int i = start; i < end; i++) local += g_deg[i];

    int lane = t & 31, wid = t >> 5;
    int v = local;
#pragma unroll
    for (int o = 1; o < 32; o <<= 1) {
        int u = __shfl_up_sync(0xffffffffu, v, o);
        if (lane >= o) v += u;
    }
    __shared__ int wsum[32];
    if (lane == 31) wsum[wid] = v;
    __syncthreads();
    if (wid == 0) {
        int wv = wsum[lane];
#pragma unroll
        for (int o = 1; o < 32; o <<= 1) {
            int u = __shfl_up_sync(0xffffffffu, wv, o);
            if (lane >= o) wv += u;
        }
        wsum[lane] = wv;
    }
    __syncthreads();
    int run = v - local + (wid > 0 ? wsum[wid - 1] : 0);

    if (t == 0) g_off[0] = 0;
    for (int i = start; i < end; i++) {
        int d = g_deg[i];
        g_deg[i] = 0;                       // reset for next graph replay
        g_cur[i] = run;
        run += d;
        g_off[i + 1] = run;
        g_dinv[i] = rsqrtf((float)(d + 1)); // +1 = self loop
    }
}

// ---------------- fill (launch #3): bucket edges by destination ------------
__global__ void fill_kernel(const int* __restrict__ ei, int E) {
    int i = blockIdx.x * blockDim.x + threadIdx.x;
    if (i < E) {
        int r = ei[i];
        int c = ei[E + i];
        int slot = atomicAdd(&g_cur[c], 1);
        g_epack[slot] = make_int2(r, __float_as_int(g_dinv[r] * g_dinv[c]));
    }
}

// ---------------- fused agg + conv (launch #4: PROFILED) -------------------
// Per 128-row block:
//   Phase 1: CSR gather (warp-per-16-nodes, float4 lanes 0..23) computes
//            h = 0.9*(dinv^2 xc + sum w xc[row]) + 0.1*x0, written k-major
//            into smem Hsk.
//   Phase 2: GEMM h @ W', W' = (1-beta)I + beta*W (identity folded into the
//            staged tile) -> acc IS h2. fc1-style 8x6 register tile.
//   Phase 3: BN stats from acc + store h2 to g_hb.
// Dynamic smem: Hsk[96*132] + Ws[32*98] + sSum[96] + sSq[96] = 64000 B.
__global__ __launch_bounds__(256, 2) void conv_agg_kernel(
    const float* __restrict__ W, float beta, int N)
{
    extern __shared__ float smem[];
    float* Hsk  = smem;                 // [k][row] stride 132
    float* Wsk  = smem + 96 * 132;      // [k][col] stride 98
    float* sSum = Wsk + 32 * 98;
    float* sSq  = sSum + 96;

    const int tid = threadIdx.x;
    const int row0 = blockIdx.x * 128;
    const int warp = tid >> 5, lane = tid & 31;

    if (tid < 96) { sSum[tid] = 0.f; sSq[tid] = 0.f; }

    // -------- Phase 1: gather --------
    const float4* xc4 = (const float4*)g_xc;
    for (int q = 0; q < 16; q++) {
        int lr = warp * 16 + q;
        int n  = row0 + lr;
        if (lane < 24) {
            float4 h = make_float4(0.f, 0.f, 0.f, 0.f);
            if (n < N) {
                float w0 = g_dinv[n];
                w0 *= w0;
                float4 v = xc4[n * HC4 + lane];
                float a0 = w0 * v.x, a1 = w0 * v.y, a2 = w0 * v.z, a3 = w0 * v.w;
                int s = g_off[n], e = g_off[n + 1];
                for (int i = s; i < e; i++) {
                    int2 ep = g_epack[i];
                    float w = __int_as_float(ep.y);
                    float4 xv = xc4[ep.x * HC4 + lane];
                    a0 = fmaf(w, xv.x, a0); a1 = fmaf(w, xv.y, a1);
                    a2 = fmaf(w, xv.z, a2); a3 = fmaf(w, xv.w, a3);
                }
                float4 x0v = ((const float4*)g_x0)[n * HC4 + lane];
                h.x = 0.9f * a0 + 0.1f * x0v.x;
                h.y = 0.9f * a1 + 0.1f * x0v.y;
                h.z = 0.9f * a2 + 0.1f * x0v.z;
                h.w = 0.9f * a3 + 0.1f * x0v.w;
            }
            int kb = 4 * lane;
            Hsk[(kb + 0) * 132 + lr] = h.x;
            Hsk[(kb + 1) * 132 + lr] = h.y;
            Hsk[(kb + 2) * 132 + lr] = h.z;
            Hsk[(kb + 3) * 132 + lr] = h.w;
        }
    }
    __syncthreads();

    // -------- Phase 2: GEMM h @ ((1-b)I + b W) --------
    const int tx = tid & 15, ty = tid >> 4;
    const float onemb = 1.f - beta;
    float acc[8][6];
#pragma unroll
    for (int r = 0; r < 8; r++)
#pragma unroll
        for (int c = 0; c < 6; c++) acc[r][c] = 0.f;

    for (int kc = 0; kc < H; kc += 32) {
        {
            const float* wp = W + (size_t)kc * H + tid * 12;
#pragma unroll
            for (int m = 0; m < 3; m++) {
                float4 v = *(const float4*)(wp + 4 * m);
                int f = tid * 12 + 4 * m;
                int k = f / 96, j = f - 96 * k;
                int gk = kc + k;
                Wsk[k * 98 + j + 0] = beta * v.x + (gk == j + 0 ? onemb : 0.f);
                Wsk[k * 98 + j + 1] = beta * v.y + (gk == j + 1 ? onemb : 0.f);
                Wsk[k * 98 + j + 2] = beta * v.z + (gk == j + 2 ? onemb : 0.f);
                Wsk[k * 98 + j + 3] = beta * v.w + (gk == j + 3 ? onemb : 0.f);
            }
        }
        __syncthreads();
#pragma unroll 8
        for (int kk = 0; kk < 32; kk++) {
            const float* arow = &Hsk[(kc + kk) * 132 + ty * 8];
            float4 A0 = *(const float4*)(arow);
            float4 A1 = *(const float4*)(arow + 4);
            const float* brow = &Wsk[kk * 98 + tx * 6];
            float2 B0 = *(const float2*)(brow);
            float2 B1 = *(const float2*)(brow + 2);
            float2 B2 = *(const float2*)(brow + 4);
            float a[8] = {A0.x, A0.y, A0.z, A0.w, A1.x, A1.y, A1.z, A1.w};
            float bv[6] = {B0.x, B0.y, B1.x, B1.y, B2.x, B2.y};
#pragma unroll
            for (int r = 0; r < 8; r++)
#pragma unroll
                for (int c = 0; c < 6; c++) acc[r][c] = fmaf(a[r], bv[c], acc[r][c]);
        }
        __syncthreads();
    }

    // -------- Phase 3: BN stats + store h2 --------
    float ls[6] = {0, 0, 0, 0, 0, 0};
    float lq[6] = {0, 0, 0, 0, 0, 0};
#pragma unroll
    for (int r = 0; r < 8; r++) {
        int gr = row0 + ty * 8 + r;
#pragma unroll
        for (int c = 0; c < 6; c++) {
            float h2 = acc[r][c];
            if (gr >= N) h2 = 0.f;               // zero contribution to stats
            ls[c] += h2;
            lq[c] += h2 * h2;
            if (gr < N) g_hb[(size_t)gr * H + tx * 6 + c] = h2;
        }
    }
#pragma unroll
    for (int c = 0; c < 6; c++) {
        atomicAdd(&sSum[tx * 6 + c], ls[c]);
        atomicAdd(&sSq[tx * 6 + c],  lq[c]);
    }
    __syncthreads();
    if (tid < 96) {
        atomicAdd(&g_stats[tid],      sSum[tid]);
        atomicAdd(&g_stats[96 + tid], sSq[tid]);
    }
}

// ---------------- BN finalize (also re-zeroes stats for next layer) --------
__global__ void bnfin_kernel(const float* __restrict__ gamma,
                             const float* __restrict__ bb, float invN)
{
    int j = threadIdx.x;
    if (j < H) {
        float sum = g_stats[j];
        float sq  = g_stats[H + j];
        g_stats[j] = 0.f;
        g_stats[H + j] = 0.f;
        float mean = sum * invN;
        float var  = sq * invN - mean * mean;
        float sc   = gamma[j] * rsqrtf(var + 1e-5f);
        g_bn[j]     = sc;
        g_bn[H + j] = bb[j] - mean * sc;
    }
}

// ---------------- normalize + relu -> xc -----------------------------------
__global__ void norm_relu_kernel(int N) {
    int i = blockIdx.x * blockDim.x + threadIdx.x;
    int total = N * HC4;
    if (i >= total) return;
    int j4 = i % HC4;
    float4 h  = ((const float4*)g_hb)[i];
    float4 sc = ((const float4*)g_bn)[j4];
    float4 sh = ((const float4*)(g_bn + H))[j4];
    float4 o;
    o.x = fmaxf(h.x * sc.x + sh.x, 0.f);
    o.y = fmaxf(h.y * sc.y + sh.y, 0.f);
    o.z = fmaxf(h.z * sc.z + sh.z, 0.f);
    o.w = fmaxf(h.w * sc.w + sh.w, 0.f);
    ((float4*)g_xc)[i] = o;
}

// ---------------- fc2: [N,96] @ [96,40] + bias -----------------------------
__global__ __launch_bounds__(256) void fc2_kernel(
    const float* __restrict__ W2, const float* __restrict__ B2,
    float* __restrict__ out, int N)
{
    __shared__ float Ws[96 * 40];
    int tid = threadIdx.x;
    for (int i = tid; i < 96 * 40; i += 256) Ws[i] = W2[i];
    __syncthreads();
    int warp = tid >> 5, lane = tid & 31;
    int row = blockIdx.x * 8 + warp;
    if (row >= N) return;
    const float* xr = g_xc + (size_t)row * H;
    float a0 = 0.f, a1 = 0.f;
#pragma unroll
    for (int k = 0; k < 96; k++) {
        float xv = xr[k];
        a0 += xv * Ws[k * 40 + lane];
        if (lane < 8) a1 += xv * Ws[k * 40 + 32 + lane];
    }
    out[(size_t)row * OUTF + lane] = a0 + B2[lane];
    if (lane < 8) out[(size_t)row * OUTF + 32 + lane] = a1 + B2[32 + lane];
}

// ---------------- launch ----------------------------------------------------
extern "C" void kernel_launch(void* const* d_in, const int* in_sizes, int n_in,
                              void* d_out, int out_size)
{
    const float* x     = (const float*)d_in[0];
    const int*   ei    = (const int*)d_in[1];   // int32! (JAX x64 disabled)
    const float* fc1w  = (const float*)d_in[2];
    const float* fc1b  = (const float*)d_in[3];
    const float* convw = (const float*)d_in[4];
    const float* bng   = (const float*)d_in[5];
    const float* bnb   = (const float*)d_in[6];
    const float* fc2w  = (const float*)d_in[7];
    const float* fc2b  = (const float*)d_in[8];
    float*       out   = (float*)d_out;

    int N = in_sizes[0] / IN_F;
    int E = in_sizes[1] / 2;

    int fc1Blocks  = (N + 127) / 128;
    int degBlocks  = (E + 255) / 256;
    const int CONV_SMEM = (96 * 132 + 32 * 98 + 2 * 96) * 4;   // 64000 B

    // Idempotent; not a stream op, safe under graph capture.
    cudaFuncSetAttribute(conv_agg_kernel,
                         cudaFuncAttributeMaxDynamicSharedMemorySize, CONV_SMEM);

    // Launch order: fc1+deg(1), scan(2), fill(3), conv_agg(4: profiled slot)
    fc1_deg_kernel<<<fc1Blocks + degBlocks, 256>>>(x, fc1w, fc1b, N, ei, E, fc1Blocks);
    scan_dinv_kernel<<<1, 1024>>>(N);
    fill_kernel<<<degBlocks, 256>>>(ei, E);

    const double THETA = 0.5;
    int totN = N * HC4;
    for (int l = 0; l < 3; l++) {
        float beta = (float)log(THETA / (double)(l + 1) + 1.0);
        conv_agg_kernel<<<fc1Blocks, 256, CONV_SMEM>>>(convw + (size_t)l * H * H, beta, N);
        bnfin_kernel<<<1, 96>>>(bng + l * H, bnb + l * H, 1.f / (float)N);
        norm_relu_kernel<<<(totN + 255) / 256, 256>>>(N);
    }
    fc2_kernel<<<(N + 7) / 8, 256>>>(fc2w, fc2b, out, N);
}

// round 15
// speedup vs baseline: 1.1817x; 1.1817x over previous
#include <cuda_runtime.h>
#include <math.h>

// Problem shapes (fixed for this problem instance)
static constexpr int IN_F = 256;
static constexpr int H    = 96;
static constexpr int OUTF = 40;
static constexpr int NMAX = 50000;
static constexpr int EMAX = 800000;
static constexpr int HC4  = H / 4;   // 24 float4 chunks per row

// ---------------- scratch (device globals; no allocation allowed) ----------
__device__ float g_x0[(size_t)NMAX * H];   // fc1 output (initial residual)
__device__ float g_xc[(size_t)NMAX * H];   // current activation
__device__ float g_hb[(size_t)NMAX * H];   // h / h2 buffer
__device__ float g_dinv[NMAX];
__device__ int   g_deg[NMAX];              // zero-init at load; scan re-zeroes
__device__ int   g_off[NMAX + 1];          // CSR offsets (by dst/col)
__device__ int   g_cur[NMAX];              // fill cursors
__device__ int2  g_epack[EMAX];            // {src row, bits(weight)} CSR-ordered
__device__ float g_stats[2 * H];           // sum, sumsq (zeroed by bnfin)
__device__ float g_bn[2 * H];              // scale, shift per feature

// ---------------- fused fc1 + degree count (launch #1) ---------------------
__global__ __launch_bounds__(256, 2) void fc1_deg_kernel(
    const float* __restrict__ X, const float* __restrict__ W,
    const float* __restrict__ B, int N,
    const int* __restrict__ ei, int E, int fc1Blocks)
{
    if (blockIdx.x >= fc1Blocks) {
        int i = (blockIdx.x - fc1Blocks) * 256 + threadIdx.x;
        if (i < E) atomicAdd(&g_deg[ei[E + i]], 1);
        return;
    }
    __shared__ float Xs[32][132];   // [k][row]
    __shared__ float Ws[32][98];    // [k][col]
    const int tid = threadIdx.x;
    const int tx = tid & 15, ty = tid >> 4;
    const int row0 = blockIdx.x * 128;
    const int lr   = tid & 127;
    const int kgrp = tid >> 7;

    float acc[8][6];
#pragma unroll
    for (int r = 0; r < 8; r++)
#pragma unroll
        for (int c = 0; c < 6; c++) acc[r][c] = 0.f;

    for (int kc = 0; kc < IN_F; kc += 32) {
        {
            int gr = row0 + lr;
            const float* xp = X + (size_t)gr * IN_F + kc + kgrp * 16;
#pragma unroll
            for (int m = 0; m < 4; m++) {
                float4 v = (gr < N) ? *(const float4*)(xp + 4 * m)
                                    : make_float4(0.f, 0.f, 0.f, 0.f);
                int k = kgrp * 16 + 4 * m;
                Xs[k + 0][lr] = v.x;
                Xs[k + 1][lr] = v.y;
                Xs[k + 2][lr] = v.z;
                Xs[k + 3][lr] = v.w;
            }
        }
        {
            const float* wp = W + (size_t)kc * H + tid * 12;
#pragma unroll
            for (int m = 0; m < 3; m++) {
                float4 v = *(const float4*)(wp + 4 * m);
                int f = tid * 12 + 4 * m;
                int k = f / 96, j = f - 96 * k;
                Ws[k][j + 0] = v.x;
                Ws[k][j + 1] = v.y;
                Ws[k][j + 2] = v.z;
                Ws[k][j + 3] = v.w;
            }
        }
        __syncthreads();
#pragma unroll 8
        for (int kk = 0; kk < 32; kk++) {
            float4 A0 = *(const float4*)&Xs[kk][ty * 8];
            float4 A1 = *(const float4*)&Xs[kk][ty * 8 + 4];
            float2 B0 = *(const float2*)&Ws[kk][tx * 6];
            float2 B1 = *(const float2*)&Ws[kk][tx * 6 + 2];
            float2 B2 = *(const float2*)&Ws[kk][tx * 6 + 4];
            float a[8] = {A0.x, A0.y, A0.z, A0.w, A1.x, A1.y, A1.z, A1.w};
            float bv[6] = {B0.x, B0.y, B1.x, B1.y, B2.x, B2.y};
#pragma unroll
            for (int r = 0; r < 8; r++)
#pragma unroll
                for (int c = 0; c < 6; c++) acc[r][c] = fmaf(a[r], bv[c], acc[r][c]);
        }
        __syncthreads();
    }
#pragma unroll
    for (int r = 0; r < 8; r++) {
        int gr = row0 + ty * 8 + r;
        if (gr < N) {
#pragma unroll
            for (int c = 0; c < 6; c++) {
                int j = tx * 6 + c;
                float v = acc[r][c] + B[j];
                v = v > 0.f ? v : 0.f;
                g_x0[(size_t)gr * H + j] = v;
                g_xc[(size_t)gr * H + j] = v;
            }
        }
    }
}

// ---------------- scan (launch #2): off/cur/dinv; re-zeroes g_deg ----------
__global__ __launch_bounds__(1024) void scan_dinv_kernel(int N) {
    const int C = (N + 1023) / 1024;
    int t = threadIdx.x;
    int start = t * C;
    int end = start + C; if (end > N) end = N;
    int local = 0;
    for (int i = start; i < end; i++) local += g_deg[i];

    int lane = t & 31, wid = t >> 5;
    int v = local;
#pragma unroll
    for (int o = 1; o < 32; o <<= 1) {
        int u = __shfl_up_sync(0xffffffffu, v, o);
        if (lane >= o) v += u;
    }
    __shared__ int wsum[32];
    if (lane == 31) wsum[wid] = v;
    __syncthreads();
    if (wid == 0) {
        int wv = wsum[lane];
#pragma unroll
        for (int o = 1; o < 32; o <<= 1) {
            int u = __shfl_up_sync(0xffffffffu, wv, o);
            if (lane >= o) wv += u;
        }
        wsum[lane] = wv;
    }
    __syncthreads();
    int run = v - local + (wid > 0 ? wsum[wid - 1] : 0);

    if (t == 0) g_off[0] = 0;
    for (int i = start; i < end; i++) {
        int d = g_deg[i];
        g_deg[i] = 0;                       // reset for next graph replay
        g_cur[i] = run;
        run += d;
        g_off[i + 1] = run;
        g_dinv[i] = rsqrtf((float)(d + 1)); // +1 = self loop
    }
}

// ---------------- fill (launch #3): bucket edges by destination ------------
__global__ void fill_kernel(const int* __restrict__ ei, int E) {
    int i = blockIdx.x * blockDim.x + threadIdx.x;
    if (i < E) {
        int r = ei[i];
        int c = ei[E + i];
        int slot = atomicAdd(&g_cur[c], 1);
        g_epack[slot] = make_int2(r, __float_as_int(g_dinv[r] * g_dinv[c]));
    }
}

// ---------------- aggregation (launch #4: PROFILED control, 39us known) ----
// CSR gather, 24-lane group per node (one float4 lane each), 16 nodes/block.
// hb[n] = 0.9 * (dinv[n]^2 * xc[n] + sum_e w_e * xc[row_e]) + 0.1 * x0[n]
__global__ __launch_bounds__(384) void agg_kernel(int N) {
    int f4 = threadIdx.x;                    // 0..23
    int n  = blockIdx.x * 16 + threadIdx.y;
    if (n >= N) return;
    const float4* xc4 = (const float4*)g_xc;
    float w0 = g_dinv[n];
    w0 *= w0;
    float4 v = xc4[n * HC4 + f4];
    float4 acc = make_float4(w0 * v.x, w0 * v.y, w0 * v.z, w0 * v.w);
    int s = g_off[n], e = g_off[n + 1];
    for (int i = s; i < e; i++) {
        int2 ep = g_epack[i];
        float w = __int_as_float(ep.y);
        float4 xv = xc4[ep.x * HC4 + f4];
        acc.x += w * xv.x; acc.y += w * xv.y;
        acc.z += w * xv.z; acc.w += w * xv.w;
    }
    float4 x0v = ((const float4*)g_x0)[n * HC4 + f4];
    float4 h;
    h.x = 0.9f * acc.x + 0.1f * x0v.x;
    h.y = 0.9f * acc.y + 0.1f * x0v.y;
    h.z = 0.9f * acc.z + 0.1f * x0v.z;
    h.w = 0.9f * acc.w + 0.1f * x0v.w;
    ((float4*)g_hb)[n * HC4 + f4] = h;
}

// ---------------- conv: h2 = h @ ((1-b)I + b W), fused BN stats ------------
// 128-row tile, 8x6 register tile (fc1's measured-fast structure). Identity
// folded into the staged weight tile -> NO epilogue Hsk re-read: stats and
// the h2 store come straight from acc. In-place on g_hb.
__global__ __launch_bounds__(256, 2) void conv_kernel(
    const float* __restrict__ W, float beta, int N)
{
    extern __shared__ float smem[];
    float* Hsk  = smem;                 // [k][row] stride 132, 96 k-rows
    float* Wsk  = smem + 96 * 132;      // [k][col] stride 98, 32 k-rows
    float* sSum = Wsk + 32 * 98;
    float* sSq  = sSum + 96;

    const int tid = threadIdx.x;
    const int tx = tid & 15, ty = tid >> 4;
    const int row0 = blockIdx.x * 128;
    const int lr   = tid & 127;
    const int kgrp = tid >> 7;          // 0/1 -> k base 0/48

    if (tid < 96) { sSum[tid] = 0.f; sSq[tid] = 0.f; }

    // Load h tile (128 rows x 96 feats) k-major: 12 float4 per thread.
    {
        int gr = row0 + lr;
        const float* hp = g_hb + (size_t)gr * H + kgrp * 48;
#pragma unroll
        for (int m = 0; m < 12; m++) {
            float4 v = (gr < N) ? *(const float4*)(hp + 4 * m)
                                : make_float4(0.f, 0.f, 0.f, 0.f);
            int k = kgrp * 48 + 4 * m;
            Hsk[(k + 0) * 132 + lr] = v.x;
            Hsk[(k + 1) * 132 + lr] = v.y;
            Hsk[(k + 2) * 132 + lr] = v.z;
            Hsk[(k + 3) * 132 + lr] = v.w;
        }
    }

    const float onemb = 1.f - beta;
    float acc[8][6];
#pragma unroll
    for (int r = 0; r < 8; r++)
#pragma unroll
        for (int c = 0; c < 6; c++) acc[r][c] = 0.f;

    for (int kc = 0; kc < H; kc += 32) {
        {
            const float* wp = W + (size_t)kc * H + tid * 12;
#pragma unroll
            for (int m = 0; m < 3; m++) {
                float4 v = *(const float4*)(wp + 4 * m);
                int f = tid * 12 + 4 * m;
                int k = f / 96, j = f - 96 * k;
                int gk = kc + k;
                Wsk[k * 98 + j + 0] = beta * v.x + (gk == j + 0 ? onemb : 0.f);
                Wsk[k * 98 + j + 1] = beta * v.y + (gk == j + 1 ? onemb : 0.f);
                Wsk[k * 98 + j + 2] = beta * v.z + (gk == j + 2 ? onemb : 0.f);
                Wsk[k * 98 + j + 3] = beta * v.w + (gk == j + 3 ? onemb : 0.f);
            }
        }
        __syncthreads();
#pragma unroll 8
        for (int kk = 0; kk < 32; kk++) {
            const float* arow = &Hsk[(kc + kk) * 132 + ty * 8];
            float4 A0 = *(const float4*)(arow);
            float4 A1 = *(const float4*)(arow + 4);
            const float* brow = &Wsk[kk * 98 + tx * 6];
            float2 B0 = *(const float2*)(brow);
            float2 B1 = *(const float2*)(brow + 2);
            float2 B2 = *(const float2*)(brow + 4);
            float a[8] = {A0.x, A0.y, A0.z, A0.w, A1.x, A1.y, A1.z, A1.w};
            float bv[6] = {B0.x, B0.y, B1.x, B1.y, B2.x, B2.y};
#pragma unroll
            for (int r = 0; r < 8; r++)
#pragma unroll
                for (int c = 0; c < 6; c++) acc[r][c] = fmaf(a[r], bv[c], acc[r][c]);
        }
        __syncthreads();
    }

    // Epilogue: BN stats + store h2 straight from acc (no smem re-read).
    float ls[6] = {0, 0, 0, 0, 0, 0};
    float lq[6] = {0, 0, 0, 0, 0, 0};
#pragma unroll
    for (int r = 0; r < 8; r++) {
        int gr = row0 + ty * 8 + r;
#pragma unroll
        for (int c = 0; c < 6; c++) {
            float h2 = acc[r][c];
            if (gr >= N) h2 = 0.f;               // zero contribution to stats
            ls[c] += h2;
            lq[c] += h2 * h2;
            if (gr < N) g_hb[(size_t)gr * H + tx * 6 + c] = h2;
        }
    }
#pragma unroll
    for (int c = 0; c < 6; c++) {
        atomicAdd(&sSum[tx * 6 + c], ls[c]);
        atomicAdd(&sSq[tx * 6 + c],  lq[c]);
    }
    __syncthreads();
    if (tid < 96) {
        atomicAdd(&g_stats[tid],      sSum[tid]);
        atomicAdd(&g_stats[96 + tid], sSq[tid]);
    }
}

// ---------------- BN finalize (also re-zeroes stats for next layer) --------
__global__ void bnfin_kernel(const float* __restrict__ gamma,
                             const float* __restrict__ bb, float invN)
{
    int j = threadIdx.x;
    if (j < H) {
        float sum = g_stats[j];
        float sq  = g_stats[H + j];
        g_stats[j] = 0.f;
        g_stats[H + j] = 0.f;
        float mean = sum * invN;
        float var  = sq * invN - mean * mean;
        float sc   = gamma[j] * rsqrtf(var + 1e-5f);
        g_bn[j]     = sc;
        g_bn[H + j] = bb[j] - mean * sc;
    }
}

// ---------------- normalize + relu -> xc -----------------------------------
__global__ void norm_relu_kernel(int N) {
    int i = blockIdx.x * blockDim.x + threadIdx.x;
    int total = N * HC4;
    if (i >= total) return;
    int j4 = i % HC4;
    float4 h  = ((const float4*)g_hb)[i];
    float4 sc = ((const float4*)g_bn)[j4];
    float4 sh = ((const float4*)(g_bn + H))[j4];
    float4 o;
    o.x = fmaxf(h.x * sc.x + sh.x, 0.f);
    o.y = fmaxf(h.y * sc.y + sh.y, 0.f);
    o.z = fmaxf(h.z * sc.z + sh.z, 0.f);
    o.w = fmaxf(h.w * sc.w + sh.w, 0.f);
    ((float4*)g_xc)[i] = o;
}

// ---------------- fc2: [N,96] @ [96,40] + bias -----------------------------
__global__ __launch_bounds__(256) void fc2_kernel(
    const float* __restrict__ W2, const float* __restrict__ B2,
    float* __restrict__ out, int N)
{
    __shared__ float Ws[96 * 40];
    int tid = threadIdx.x;
    for (int i = tid; i < 96 * 40; i += 256) Ws[i] = W2[i];
    __syncthreads();
    int warp = tid >> 5, lane = tid & 31;
    int row = blockIdx.x * 8 + warp;
    if (row >= N) return;
    const float* xr = g_xc + (size_t)row * H;
    float a0 = 0.f, a1 = 0.f;
#pragma unroll
    for (int k = 0; k < 96; k++) {
        float xv = xr[k];
        a0 += xv * Ws[k * 40 + lane];
        if (lane < 8) a1 += xv * Ws[k * 40 + 32 + lane];
    }
    out[(size_t)row * OUTF + lane] = a0 + B2[lane];
    if (lane < 8) out[(size_t)row * OUTF + 32 + lane] = a1 + B2[32 + lane];
}

// ---------------- launch ----------------------------------------------------
extern "C" void kernel_launch(void* const* d_in, const int* in_sizes, int n_in,
                              void* d_out, int out_size)
{
    const float* x     = (const float*)d_in[0];
    const int*   ei    = (const int*)d_in[1];   // int32! (JAX x64 disabled)
    const float* fc1w  = (const float*)d_in[2];
    const float* fc1b  = (const float*)d_in[3];
    const float* convw = (const float*)d_in[4];
    const float* bng   = (const float*)d_in[5];
    const float* bnb   = (const float*)d_in[6];
    const float* fc2w  = (const float*)d_in[7];
    const float* fc2b  = (const float*)d_in[8];
    float*       out   = (float*)d_out;

    int N = in_sizes[0] / IN_F;
    int E = in_sizes[1] / 2;

    int fc1Blocks = (N + 127) / 128;
    int degBlocks = (E + 255) / 256;
    const int CONV_SMEM = (96 * 132 + 32 * 98 + 2 * 96) * 4;   // 64000 B

    // Idempotent; not a stream op, safe under graph capture.
    cudaFuncSetAttribute(conv_kernel,
                         cudaFuncAttributeMaxDynamicSharedMemorySize, CONV_SMEM);

    // Launch order: fc1+deg(1), scan(2), fill(3), agg(4: profiled control)
    fc1_deg_kernel<<<fc1Blocks + degBlocks, 256>>>(x, fc1w, fc1b, N, ei, E, fc1Blocks);
    scan_dinv_kernel<<<1, 1024>>>(N);
    fill_kernel<<<degBlocks, 256>>>(ei, E);

    const double THETA = 0.5;
    int totN = N * HC4;
    for (int l = 0; l < 3; l++) {
        agg_kernel<<<(N + 15) / 16, dim3(24, 16)>>>(N);
        float beta = (float)log(THETA / (double)(l + 1) + 1.0);
        conv_kernel<<<fc1Blocks, 256, CONV_SMEM>>>(convw + (size_t)l * H * H, beta, N);
        bnfin_kernel<<<1, 96>>>(bng + l * H, bnb + l * H, 1.f / (float)N);
        norm_relu_kernel<<<(totN + 255) / 256, 256>>>(N);
    }
    fc2_kernel<<<(N + 7) / 8, 256>>>(fc2w, fc2b, out, N);
}